// round 10
// baseline (speedup 1.0000x reference)
#include <cuda_runtime.h>

// CFConv: y[i] = sum_{e: idx_i[e]==i} x[idx_j[e]] * Wij[e]
// x:[50000,64] f32, Wij:[E=1.25M,64] f32, idx_i sorted.
//
// R10: R8's dual cp.async SMEM ring (W stream + x gather) with amortized
// fixed costs: HALF 64->128 (half the prologue/boundary cost per edge),
// D 6->8, main loop unrolled x2 (one wait_group per 2 edges; unconditional
// commit_group keeps the group-count invariant). Half-warp float4 lanes;
// sorted-segment register accumulation; plain stores for interior segments;
// red.global.add.v4.f32 at task boundaries.

#define FEAT   64
#define F4     (FEAT / 4)      // 16 float4 per feature row
#define HALF   128             // edges per half-warp task
#define CHUNK  (2 * HALF)      // edges per warp
#define D      8               // ring depth (stages)
#define WPB    2               // warps per block
#define TPB    (WPB * 32)

#define CP_COMMIT()  asm volatile("cp.async.commit_group;" ::: "memory")
#define CP_WAIT(n)   asm volatile("cp.async.wait_group %0;" :: "n"(n) : "memory")

__device__ __forceinline__ void red_add_f4(float* p, float4 v) {
    asm volatile("red.global.add.v4.f32 [%0], {%1,%2,%3,%4};"
                 :: "l"(p), "f"(v.x), "f"(v.y), "f"(v.z), "f"(v.w)
                 : "memory");
}

__device__ __forceinline__ void fma4(float4& a, float4 x, float4 w) {
    a.x = fmaf(x.x, w.x, a.x);
    a.y = fmaf(x.y, w.y, a.y);
    a.z = fmaf(x.z, w.z, a.z);
    a.w = fmaf(x.w, w.w, a.w);
}

__device__ __forceinline__ void flush(float* __restrict__ y, int seg, int fl,
                                      float4 acc, bool& first)
{
    float* dst = y + (size_t)seg * FEAT + fl * 4;
    if (first) { red_add_f4(dst, acc); first = false; }
    else       { *reinterpret_cast<float4*>(dst) = acc; }  // exclusive interior
}

__device__ __forceinline__ void cp16(void* smem_dst, const void* gmem_src) {
    unsigned           ds = (unsigned)__cvta_generic_to_shared(smem_dst);
    unsigned long long gs = (unsigned long long)__cvta_generic_to_global(gmem_src);
    asm volatile("cp.async.cg.shared.global [%0], [%1], 16;"
                 :: "r"(ds), "l"(gs) : "memory");
}

template <typename T>
__device__ __forceinline__ void pf_l1(const T* p) {
    asm volatile("prefetch.global.L1 [%0];" :: "l"(p));
}

template <typename IdxT>
__device__ __forceinline__ void cfconv_body(
    const float4* __restrict__ X4, const float4* __restrict__ W4,
    const IdxT* __restrict__ idx_i, const IdxT* __restrict__ idx_j,
    float* __restrict__ y,
    float4 (&sW)[WPB][D][32], float4 (&sX)[WPB][D][32],
    int w, int lane, int fl, long long s, int cnt)
{
    const float4* wp = W4 + (size_t)s * F4 + fl;

    int    prev;
    bool   first = true;               // first segment may start before s
    float4 acc   = make_float4(0.f, 0.f, 0.f, 0.f);

    if (cnt == HALF) {
        // -------- pipelined full-task path --------
        // prologue: fill all D stages (one commit group per stage)
        #pragma unroll
        for (int d = 0; d < D; ++d) {
            int jj = (int)idx_j[s + d];
            cp16(&sW[w][d][lane], wp + (size_t)d * F4);
            cp16(&sX[w][d][lane], X4 + (size_t)jj * F4 + fl);
            CP_COMMIT();
        }
        int ci  = (int)idx_i[s];
        prev    = ci;
        int pj0 = (int)idx_j[s + D];       // gather idx for first prefetches
        int pj1 = (int)idx_j[s + D + 1];

        #pragma unroll 1
        for (int k = 0; k < HALF; k += 2) {
            CP_WAIT(D - 2);                 // stages k and k+1 complete
            int st0 = k & (D - 1);
            int st1 = (k + 1) & (D - 1);
            float4 wv0 = sW[w][st0][lane];
            float4 xv0 = sX[w][st0][lane];
            float4 wv1 = sW[w][st1][lane];
            float4 xv1 = sX[w][st1][lane];

            // prefetch edges k+D, k+D+1 into the slots just consumed;
            // commits are unconditional (possibly empty) to keep exactly D
            // groups outstanding for CP_WAIT's accounting.
            if (k + D < HALF) {
                cp16(&sW[w][st0][lane], wp + (size_t)(k + D) * F4);
                cp16(&sX[w][st0][lane], X4 + (size_t)pj0 * F4 + fl);
            }
            CP_COMMIT();
            if (k + D + 1 < HALF) {
                cp16(&sW[w][st1][lane], wp + (size_t)(k + D + 1) * F4);
                cp16(&sX[w][st1][lane], X4 + (size_t)pj1 * F4 + fl);
                pf_l1(idx_i + s + k + D);   // keep idx_i line L1-hot
            }
            CP_COMMIT();

            // stage indices for the next iteration (clamped; L1 hits)
            int ci1 = (int)idx_i[s + k + 1];
            int nc  = k + 2;     if (nc > HALF - 1) nc = HALF - 1;
            int np0 = k + D + 2; if (np0 > HALF - 1) np0 = HALF - 1;
            int np1 = k + D + 3; if (np1 > HALF - 1) np1 = HALF - 1;
            int ci2 = (int)idx_i[s + nc];
            pj0 = (int)idx_j[s + np0];
            pj1 = (int)idx_j[s + np1];

            // consume edge k
            if (ci != prev) {
                flush(y, prev, fl, acc, first);
                acc  = make_float4(0.f, 0.f, 0.f, 0.f);
                prev = ci;
            }
            fma4(acc, xv0, wv0);
            // consume edge k+1
            if (ci1 != prev) {
                flush(y, prev, fl, acc, first);
                acc  = make_float4(0.f, 0.f, 0.f, 0.f);
                prev = ci1;
            }
            fma4(acc, xv1, wv1);
            ci = ci2;
        }
    } else {
        // -------- scalar tail path (at most one partial task) --------
        int    ic = (int)idx_i[s];
        int    jc = (int)idx_j[s];
        float4 wc = __ldcs(wp);
        float4 xc = X4[(size_t)jc * F4 + fl];
        prev = ic;
        for (int k = 1; k < cnt; ++k) {
            int    in_ = (int)idx_i[s + k];
            int    jn  = (int)idx_j[s + k];
            float4 wn  = __ldcs(wp + (size_t)k * F4);
            float4 xn  = X4[(size_t)jn * F4 + fl];
            if (ic != prev) {
                flush(y, prev, fl, acc, first);
                acc  = make_float4(0.f, 0.f, 0.f, 0.f);
                prev = ic;
            }
            fma4(acc, xc, wc);
            ic = in_; wc = wn; xc = xn;
        }
        if (ic != prev) {
            flush(y, prev, fl, acc, first);
            acc  = make_float4(0.f, 0.f, 0.f, 0.f);
            prev = ic;
        }
        fma4(acc, xc, wc);
    }

    // final segment may extend into the next task -> atomic
    red_add_f4(y + (size_t)prev * FEAT + fl * 4, acc);
}

__global__ __launch_bounds__(TPB) void cfconv_kernel(
    const float4* __restrict__ X4, const float4* __restrict__ W4,
    const void* __restrict__ ii_p, const void* __restrict__ jj_p,
    float* __restrict__ y, int E)
{
    __shared__ float4 sW[WPB][D][32];
    __shared__ float4 sX[WPB][D][32];

    int tid  = threadIdx.x;
    int w    = tid >> 5;
    int lane = tid & 31;
    int half = lane >> 4;
    int fl   = lane & 15;

    int gwarp = blockIdx.x * WPB + w;
    long long base = (long long)gwarp * CHUNK;
    if (base >= E) return;
    long long s = base + (long long)half * HALF;
    if (s >= E) return;
    long long se = s + HALF; if (se > E) se = E;
    int cnt = (int)(se - s);

    // dtype probe (uniform): LE int64 -> int32 word at odd position (E/2)|1 is
    // a zero high word; int32 -> sorted idx_i median ~N/2 != 0.
    int probe = reinterpret_cast<const int*>(ii_p)[(E / 2) | 1];
    if (probe == 0) {
        cfconv_body<long long>(X4, W4,
                               reinterpret_cast<const long long*>(ii_p),
                               reinterpret_cast<const long long*>(jj_p),
                               y, sW, sX, w, lane, fl, s, cnt);
    } else {
        cfconv_body<int>(X4, W4,
                         reinterpret_cast<const int*>(ii_p),
                         reinterpret_cast<const int*>(jj_p),
                         y, sW, sX, w, lane, fl, s, cnt);
    }
}

extern "C" void kernel_launch(void* const* d_in, const int* in_sizes, int n_in,
                              void* d_out, int out_size)
{
    const float* x   = (const float*)d_in[0];   // [N, 64]
    const float* Wij = (const float*)d_in[1];   // [E, 64]
    const void*  ii  = d_in[2];                 // [E] int64 or int32
    const void*  jj  = d_in[3];                 // [E] int64 or int32
    float*       y   = (float*)d_out;           // [N, 64]

    int E = in_sizes[1] / FEAT;

    // zero output (memset node — graph-capturable)
    cudaMemsetAsync(d_out, 0, (size_t)out_size * sizeof(float), 0);

    int nwarps  = (E + CHUNK - 1) / CHUNK;
    int nblocks = (nwarps + WPB - 1) / WPB;
    cfconv_kernel<<<nblocks, TPB>>>((const float4*)x, (const float4*)Wij,
                                    ii, jj, y, E);
}

// round 11
// speedup vs baseline: 1.0915x; 1.0915x over previous
#include <cuda_runtime.h>

// CFConv: y[i] = sum_{e: idx_i[e]==i} x[idx_j[e]] * Wij[e]
// x:[50000,64] f32, Wij:[E=1.25M,64] f32, idx_i sorted.
//
// R11: R8 structure, but the sequential W stream bypasses shared memory
// (direct __ldcs LDG.128, depth-3 register rotation, NO prefetch spam);
// only the random x gather uses the cp.async SMEM ring (D=8). Halves smem
// crossbar bytes/edge (the measured bottleneck: LDGSTS-write + LDS-read of
// 2KB per 2 edges = ~8 of 14.2 cyc/edge). Half-warp float4 lanes; sorted-
// segment register accumulation; plain stores for interior segments;
// red.global.add.v4.f32 at task boundaries.

#define FEAT   64
#define F4     (FEAT / 4)      // 16 float4 per feature row
#define HALF   64              // edges per half-warp task
#define CHUNK  (2 * HALF)      // edges per warp
#define D      8               // x-gather ring depth
#define WD     3               // W register pipeline depth
#define WPB    2               // warps per block
#define TPB    (WPB * 32)

__device__ __forceinline__ void red_add_f4(float* p, float4 v) {
    asm volatile("red.global.add.v4.f32 [%0], {%1,%2,%3,%4};"
                 :: "l"(p), "f"(v.x), "f"(v.y), "f"(v.z), "f"(v.w)
                 : "memory");
}

__device__ __forceinline__ void fma4(float4& a, float4 x, float4 w) {
    a.x = fmaf(x.x, w.x, a.x);
    a.y = fmaf(x.y, w.y, a.y);
    a.z = fmaf(x.z, w.z, a.z);
    a.w = fmaf(x.w, w.w, a.w);
}

__device__ __forceinline__ void flush(float* __restrict__ y, int seg, int fl,
                                      float4 acc, bool& first)
{
    float* dst = y + (size_t)seg * FEAT + fl * 4;
    if (first) { red_add_f4(dst, acc); first = false; }
    else       { *reinterpret_cast<float4*>(dst) = acc; }  // exclusive interior
}

__device__ __forceinline__ void cp16(void* smem_dst, const void* gmem_src) {
    unsigned           ds = (unsigned)__cvta_generic_to_shared(smem_dst);
    unsigned long long gs = (unsigned long long)__cvta_generic_to_global(gmem_src);
    asm volatile("cp.async.cg.shared.global [%0], [%1], 16;"
                 :: "r"(ds), "l"(gs) : "memory");
}

template <typename T>
__device__ __forceinline__ void pf_l1(const T* p) {
    asm volatile("prefetch.global.L1 [%0];" :: "l"(p));
}

template <typename IdxT>
__device__ __forceinline__ void cfconv_body(
    const float4* __restrict__ X4, const float4* __restrict__ W4,
    const IdxT* __restrict__ idx_i, const IdxT* __restrict__ idx_j,
    float* __restrict__ y,
    float4 (&sX)[WPB][D][32],
    int w, int lane, int fl, long long s, int cnt)
{
    const float4* wp = W4 + (size_t)s * F4 + fl;

    int    prev;
    bool   first = true;               // first segment may start before s
    float4 acc   = make_float4(0.f, 0.f, 0.f, 0.f);

    if (cnt == HALF) {
        // -------- pipelined full-task path --------
        // x ring prologue: fill all D stages (one commit group per stage)
        #pragma unroll
        for (int d = 0; d < D; ++d) {
            int jj = (int)idx_j[s + d];
            cp16(&sX[w][d][lane], X4 + (size_t)jj * F4 + fl);
            asm volatile("cp.async.commit_group;" ::: "memory");
        }
        // W register pipeline, depth-3 (sequential DRAM stream)
        float4 wA = __ldcs(wp);
        float4 wB = __ldcs(wp + F4);
        float4 wC = __ldcs(wp + 2 * F4);

        int ci = (int)idx_i[s];        // consume idx, depth-1 staged
        prev   = ci;
        int pj = (int)idx_j[s + D];    // gather idx for first in-loop prefetch

        for (int k = 0; k < HALF; ++k) {
            asm volatile("cp.async.wait_group %0;" :: "n"(D - 1) : "memory");
            int st = k % D;
            float4 xv = sX[w][st][lane];

            // x-gather prefetch for edge k+D into the slot just consumed
            if (k + D < HALF) {
                cp16(&sX[w][st][lane], X4 + (size_t)pj * F4 + fl);
                pf_l1(idx_i + s + k + D);      // keep idx_i line L1-hot
            }
            asm volatile("cp.async.commit_group;" ::: "memory");

            // W: issue load for k+WD (clamped in-task)
            int nw = k + WD; if (nw > HALF - 1) nw = HALF - 1;
            float4 wN = __ldcs(wp + (size_t)nw * F4);

            // stage next-iteration indices (clamped; L1 hits)
            int nc = k + 1;     if (nc > HALF - 1) nc = HALF - 1;
            int np = k + D + 1; if (np > HALF - 1) np = HALF - 1;
            int ci_n = (int)idx_i[s + nc];
            pj       = (int)idx_j[s + np];

            // consume edge k
            if (ci != prev) {
                flush(y, prev, fl, acc, first);
                acc  = make_float4(0.f, 0.f, 0.f, 0.f);
                prev = ci;
            }
            fma4(acc, xv, wA);
            ci = ci_n;
            wA = wB; wB = wC; wC = wN;
        }
    } else {
        // -------- scalar tail path (at most one partial task) --------
        int    ic = (int)idx_i[s];
        int    jc = (int)idx_j[s];
        float4 wc = __ldcs(wp);
        float4 xc = X4[(size_t)jc * F4 + fl];
        prev = ic;
        for (int k = 1; k < cnt; ++k) {
            int    in_ = (int)idx_i[s + k];
            int    jn  = (int)idx_j[s + k];
            float4 wn  = __ldcs(wp + (size_t)k * F4);
            float4 xn  = X4[(size_t)jn * F4 + fl];
            if (ic != prev) {
                flush(y, prev, fl, acc, first);
                acc  = make_float4(0.f, 0.f, 0.f, 0.f);
                prev = ic;
            }
            fma4(acc, xc, wc);
            ic = in_; wc = wn; xc = xn;
        }
        if (ic != prev) {
            flush(y, prev, fl, acc, first);
            acc  = make_float4(0.f, 0.f, 0.f, 0.f);
            prev = ic;
        }
        fma4(acc, xc, wc);
    }

    // final segment may extend into the next task -> atomic
    red_add_f4(y + (size_t)prev * FEAT + fl * 4, acc);
}

__global__ __launch_bounds__(TPB) void cfconv_kernel(
    const float4* __restrict__ X4, const float4* __restrict__ W4,
    const void* __restrict__ ii_p, const void* __restrict__ jj_p,
    float* __restrict__ y, int E)
{
    __shared__ float4 sX[WPB][D][32];

    int tid  = threadIdx.x;
    int w    = tid >> 5;
    int lane = tid & 31;
    int half = lane >> 4;
    int fl   = lane & 15;

    int gwarp = blockIdx.x * WPB + w;
    long long base = (long long)gwarp * CHUNK;
    if (base >= E) return;
    long long s = base + (long long)half * HALF;
    if (s >= E) return;
    long long se = s + HALF; if (se > E) se = E;
    int cnt = (int)(se - s);

    // dtype probe (uniform): LE int64 -> int32 word at odd position (E/2)|1 is
    // a zero high word; int32 -> sorted idx_i median ~N/2 != 0.
    int probe = reinterpret_cast<const int*>(ii_p)[(E / 2) | 1];
    if (probe == 0) {
        cfconv_body<long long>(X4, W4,
                               reinterpret_cast<const long long*>(ii_p),
                               reinterpret_cast<const long long*>(jj_p),
                               y, sX, w, lane, fl, s, cnt);
    } else {
        cfconv_body<int>(X4, W4,
                         reinterpret_cast<const int*>(ii_p),
                         reinterpret_cast<const int*>(jj_p),
                         y, sX, w, lane, fl, s, cnt);
    }
}

extern "C" void kernel_launch(void* const* d_in, const int* in_sizes, int n_in,
                              void* d_out, int out_size)
{
    const float* x   = (const float*)d_in[0];   // [N, 64]
    const float* Wij = (const float*)d_in[1];   // [E, 64]
    const void*  ii  = d_in[2];                 // [E] int64 or int32
    const void*  jj  = d_in[3];                 // [E] int64 or int32
    float*       y   = (float*)d_out;           // [N, 64]

    int E = in_sizes[1] / FEAT;

    // zero output (memset node — graph-capturable)
    cudaMemsetAsync(d_out, 0, (size_t)out_size * sizeof(float), 0);

    int nwarps  = (E + CHUNK - 1) / CHUNK;
    int nblocks = (nwarps + WPB - 1) / WPB;
    cfconv_kernel<<<nblocks, TPB>>>((const float4*)x, (const float4*)Wij,
                                    ii, jj, y, E);
}

// round 13
// speedup vs baseline: 1.3724x; 1.2574x over previous
#include <cuda_runtime.h>

// CFConv: y[i] = sum_{e: idx_i[e]==i} x[idx_j[e]] * Wij[e]
// x:[50000,64] f32, Wij:[E=1.25M,64] f32, idx_i sorted.
//
// R13 (= R12 with the asm-constant fix): R8's dual cp.async ring (W + x) with
// an instruction diet: two-phase loop (phase 1 = unconditional prefetch, no
// guards/clamps; phase 2 = last D iterations as a recursive constexpr
// template so wait_group counts are compile-time constants), D=8 so stage
// index is a single AND, stride-templated int32 index reads (int64 indices
// < 2^31 -> read low word at e*ST). Half-warp float4 lanes; sorted-segment
// register accumulation; plain stores for interior segments;
// red.global.add.v4.f32 at task boundaries.

#define FEAT   64
#define F4     (FEAT / 4)      // 16 float4 per feature row
#define HALF   64              // edges per half-warp task
#define CHUNK  (2 * HALF)      // edges per warp
#define D      8               // ring depth (power of 2)
#define WPB    2               // warps per block
#define TPB    (WPB * 32)

#define CP_COMMIT()  asm volatile("cp.async.commit_group;" ::: "memory")

template <int N>
__device__ __forceinline__ void cp_wait() {
    asm volatile("cp.async.wait_group %0;" :: "n"(N) : "memory");
}

__device__ __forceinline__ void red_add_f4(float* p, float4 v) {
    asm volatile("red.global.add.v4.f32 [%0], {%1,%2,%3,%4};"
                 :: "l"(p), "f"(v.x), "f"(v.y), "f"(v.z), "f"(v.w)
                 : "memory");
}

__device__ __forceinline__ void fma4(float4& a, float4 x, float4 w) {
    a.x = fmaf(x.x, w.x, a.x);
    a.y = fmaf(x.y, w.y, a.y);
    a.z = fmaf(x.z, w.z, a.z);
    a.w = fmaf(x.w, w.w, a.w);
}

__device__ __forceinline__ void flush(float* __restrict__ y, int seg, int fl,
                                      float4 acc, bool& first)
{
    float* dst = y + (size_t)seg * FEAT + fl * 4;
    if (first) { red_add_f4(dst, acc); first = false; }
    else       { *reinterpret_cast<float4*>(dst) = acc; }  // exclusive interior
}

__device__ __forceinline__ void cp16(void* smem_dst, const void* gmem_src) {
    unsigned           ds = (unsigned)__cvta_generic_to_shared(smem_dst);
    unsigned long long gs = (unsigned long long)__cvta_generic_to_global(gmem_src);
    asm volatile("cp.async.cg.shared.global [%0], [%1], 16;"
                 :: "r"(ds), "l"(gs) : "memory");
}

__device__ __forceinline__ void pf_l1(const void* p) {
    asm volatile("prefetch.global.L1 [%0];" :: "l"(p));
}

// Phase 2: consume the last D edges; wait counts are template constants.
template <int ST, int M>
__device__ __forceinline__ void phase2(
    const float4 (&sW)[WPB][D][32], const float4 (&sX)[WPB][D][32],
    const int* __restrict__ ii, float* __restrict__ y,
    int w, int lane, int fl, long long s,
    int& ci, int& prev, bool& first, float4& acc)
{
    if constexpr (M < D) {
        constexpr int k = HALF - D + M;
        cp_wait<D - 1 - M>();
        const int st = k & (D - 1);
        float4 wv = sW[w][st][lane];
        float4 xv = sX[w][st][lane];

        int nc = (k + 1 > HALF - 1) ? (HALF - 1) : (k + 1);  // compile-time
        int ci_n = ii[(s + nc) * ST];

        if (ci != prev) {
            flush(y, prev, fl, acc, first);
            acc  = make_float4(0.f, 0.f, 0.f, 0.f);
            prev = ci;
        }
        fma4(acc, xv, wv);
        ci = ci_n;

        phase2<ST, M + 1>(sW, sX, ii, y, w, lane, fl, s, ci, prev, first, acc);
    }
}

// ST = index element stride in int32 words (1 for int32, 2 for LE int64 whose
// values fit in the low word).
template <int ST>
__device__ __forceinline__ void cfconv_body(
    const float4* __restrict__ X4, const float4* __restrict__ W4,
    const int* __restrict__ ii, const int* __restrict__ jj,
    float* __restrict__ y,
    float4 (&sW)[WPB][D][32], float4 (&sX)[WPB][D][32],
    int w, int lane, int fl, long long s, int cnt)
{
    const float4* wp = W4 + (size_t)s * F4 + fl;

    int    prev;
    bool   first = true;               // first segment may start before s
    float4 acc   = make_float4(0.f, 0.f, 0.f, 0.f);

    if (cnt == HALF) {
        // -------- pipelined full-task path --------
        // prologue: fill all D stages (one commit group per stage)
        #pragma unroll
        for (int d = 0; d < D; ++d) {
            int j = jj[(s + d) * ST];
            cp16(&sW[w][d][lane], wp + (size_t)d * F4);
            cp16(&sX[w][d][lane], X4 + (size_t)j * F4 + fl);
            CP_COMMIT();
        }
        int ci = ii[s * ST];           // consume idx, depth-1 staged
        prev   = ci;
        int pj = jj[(s + D) * ST];     // gather idx for first in-loop prefetch

        // ---- phase 1: k in [0, HALF-D) — unconditional prefetch, no clamps
        #pragma unroll 1
        for (int k = 0; k < HALF - D; ++k) {
            cp_wait<D - 1>();
            int st = k & (D - 1);
            float4 wv = sW[w][st][lane];
            float4 xv = sX[w][st][lane];

            cp16(&sW[w][st][lane], wp + (size_t)(k + D) * F4);
            cp16(&sX[w][st][lane], X4 + (size_t)pj * F4 + fl);
            CP_COMMIT();
            pf_l1(ii + (s + k + D) * ST);          // keep idx_i line L1-hot

            // stage next-iteration indices (one clamp at the seam)
            int np = k + D + 1; if (np > HALF - 1) np = HALF - 1;
            pj = jj[(s + np) * ST];
            int ci_n = ii[(s + k + 1) * ST];

            // consume edge k
            if (ci != prev) {
                flush(y, prev, fl, acc, first);
                acc  = make_float4(0.f, 0.f, 0.f, 0.f);
                prev = ci;
            }
            fma4(acc, xv, wv);
            ci = ci_n;
        }

        // ---- phase 2: last D edges — no prefetch, constant wait counts
        phase2<ST, 0>(sW, sX, ii, y, w, lane, fl, s, ci, prev, first, acc);
    } else {
        // -------- scalar tail path (at most one partial task) --------
        int    ic = ii[s * ST];
        int    jc = jj[s * ST];
        float4 wc = __ldcs(wp);
        float4 xc = X4[(size_t)jc * F4 + fl];
        prev = ic;
        for (int k = 1; k < cnt; ++k) {
            int    in_ = ii[(s + k) * ST];
            int    jn  = jj[(s + k) * ST];
            float4 wn  = __ldcs(wp + (size_t)k * F4);
            float4 xn  = X4[(size_t)jn * F4 + fl];
            if (ic != prev) {
                flush(y, prev, fl, acc, first);
                acc  = make_float4(0.f, 0.f, 0.f, 0.f);
                prev = ic;
            }
            fma4(acc, xc, wc);
            ic = in_; wc = wn; xc = xn;
        }
        if (ic != prev) {
            flush(y, prev, fl, acc, first);
            acc  = make_float4(0.f, 0.f, 0.f, 0.f);
            prev = ic;
        }
        fma4(acc, xc, wc);
    }

    // final segment may extend into the next task -> atomic
    red_add_f4(y + (size_t)prev * FEAT + fl * 4, acc);
}

__global__ __launch_bounds__(TPB) void cfconv_kernel(
    const float4* __restrict__ X4, const float4* __restrict__ W4,
    const void* __restrict__ ii_p, const void* __restrict__ jj_p,
    float* __restrict__ y, int E)
{
    __shared__ float4 sW[WPB][D][32];
    __shared__ float4 sX[WPB][D][32];

    int tid  = threadIdx.x;
    int w    = tid >> 5;
    int lane = tid & 31;
    int half = lane >> 4;
    int fl   = lane & 15;

    int gwarp = blockIdx.x * WPB + w;
    long long base = (long long)gwarp * CHUNK;
    if (base >= E) return;
    long long s = base + (long long)half * HALF;
    if (s >= E) return;
    long long se = s + HALF; if (se > E) se = E;
    int cnt = (int)(se - s);

    // dtype probe (uniform): LE int64 -> int32 word at odd position (E/2)|1 is
    // a zero high word; int32 -> sorted idx_i median ~N/2 != 0.
    int probe = reinterpret_cast<const int*>(ii_p)[(E / 2) | 1];
    const int* ii = reinterpret_cast<const int*>(ii_p);
    const int* jj = reinterpret_cast<const int*>(jj_p);
    if (probe == 0) {
        cfconv_body<2>(X4, W4, ii, jj, y, sW, sX, w, lane, fl, s, cnt);
    } else {
        cfconv_body<1>(X4, W4, ii, jj, y, sW, sX, w, lane, fl, s, cnt);
    }
}

extern "C" void kernel_launch(void* const* d_in, const int* in_sizes, int n_in,
                              void* d_out, int out_size)
{
    const float* x   = (const float*)d_in[0];   // [N, 64]
    const float* Wij = (const float*)d_in[1];   // [E, 64]
    const void*  ii  = d_in[2];                 // [E] int64 or int32
    const void*  jj  = d_in[3];                 // [E] int64 or int32
    float*       y   = (float*)d_out;           // [N, 64]

    int E = in_sizes[1] / FEAT;

    // zero output (memset node — graph-capturable)
    cudaMemsetAsync(d_out, 0, (size_t)out_size * sizeof(float), 0);

    int nwarps  = (E + CHUNK - 1) / CHUNK;
    int nblocks = (nwarps + WPB - 1) / WPB;
    cfconv_kernel<<<nblocks, TPB>>>((const float4*)x, (const float4*)Wij,
                                    ii, jj, y, E);
}

// round 14
// speedup vs baseline: 1.3912x; 1.0136x over previous
#include <cuda_runtime.h>

// CFConv: y[i] = sum_{e: idx_i[e]==i} x[idx_j[e]] * Wij[e]
// x:[50000,64] f32, Wij:[E=1.25M,64] f32, idx_i sorted.
//
// R14: pair-stage cp.async ring — each of DS=4 ring stages holds TWO edges
// (W row pair + gathered x pair), so wait/commit/stage-index/branch overhead
// amortizes over 2 edges while MLP (8 edges in flight) and smem (16KB) match
// R13. Phase 1 has zero guards/clamps (all reads provably in-task); phase 2
// (last 4 stages) is a recursive template with compile-time wait counts and
// clamps. Half-warp float4 lanes; sorted-segment register accumulation;
// plain stores for interior segments; red.global.add.v4.f32 at boundaries.

#define FEAT   64
#define F4     (FEAT / 4)      // 16 float4 per feature row
#define HALF   64              // edges per half-warp task
#define CHUNK  (2 * HALF)      // edges per warp
#define S      (HALF / 2)      // 32 pairs per task
#define DS     4               // ring depth in pairs (8 edges in flight)
#define WPB    2               // warps per block
#define TPB    (WPB * 32)

#define CP_COMMIT()  asm volatile("cp.async.commit_group;" ::: "memory")

template <int N>
__device__ __forceinline__ void cp_wait() {
    asm volatile("cp.async.wait_group %0;" :: "n"(N) : "memory");
}

__device__ __forceinline__ void red_add_f4(float* p, float4 v) {
    asm volatile("red.global.add.v4.f32 [%0], {%1,%2,%3,%4};"
                 :: "l"(p), "f"(v.x), "f"(v.y), "f"(v.z), "f"(v.w)
                 : "memory");
}

__device__ __forceinline__ void fma4(float4& a, float4 x, float4 w) {
    a.x = fmaf(x.x, w.x, a.x);
    a.y = fmaf(x.y, w.y, a.y);
    a.z = fmaf(x.z, w.z, a.z);
    a.w = fmaf(x.w, w.w, a.w);
}

__device__ __forceinline__ void flush(float* __restrict__ y, int seg, int fl,
                                      float4 acc, bool& first)
{
    float* dst = y + (size_t)seg * FEAT + fl * 4;
    if (first) { red_add_f4(dst, acc); first = false; }
    else       { *reinterpret_cast<float4*>(dst) = acc; }  // exclusive interior
}

__device__ __forceinline__ void cp16(void* smem_dst, const void* gmem_src) {
    unsigned           ds = (unsigned)__cvta_generic_to_shared(smem_dst);
    unsigned long long gs = (unsigned long long)__cvta_generic_to_global(gmem_src);
    asm volatile("cp.async.cg.shared.global [%0], [%1], 16;"
                 :: "r"(ds), "l"(gs) : "memory");
}

// consume one edge: segment bookkeeping + fma
__device__ __forceinline__ void consume(
    float* __restrict__ y, int fl, int ei, float4 xv, float4 wv,
    int& prev, bool& first, float4& acc)
{
    if (ei != prev) {
        flush(y, prev, fl, acc, first);
        acc  = make_float4(0.f, 0.f, 0.f, 0.f);
        prev = ei;
    }
    fma4(acc, xv, wv);
}

// Phase 2: consume the last DS pairs; wait counts/clamps are compile-time.
template <int ST, int M>
__device__ __forceinline__ void phase2(
    const float4 (&sW)[WPB][DS][2][32], const float4 (&sX)[WPB][DS][2][32],
    const int* __restrict__ ii, float* __restrict__ y,
    int w, int lane, int fl, long long s,
    int& ci, int& prev, bool& first, float4& acc)
{
    if constexpr (M < DS) {
        constexpr int k  = S - DS + M;           // pair index
        constexpr int st = k & (DS - 1);
        cp_wait<DS - 1 - M>();
        float4 wv0 = sW[w][st][0][lane];
        float4 xv0 = sX[w][st][0][lane];
        float4 wv1 = sW[w][st][1][lane];
        float4 xv1 = sX[w][st][1][lane];

        constexpr int e1 = 2 * k + 1;                          // <= 63
        constexpr int e2 = (2 * k + 2 > HALF - 1) ? (HALF - 1) : (2 * k + 2);
        int ci1 = ii[(s + e1) * ST];
        int ci2 = ii[(s + e2) * ST];

        consume(y, fl, ci,  xv0, wv0, prev, first, acc);
        consume(y, fl, ci1, xv1, wv1, prev, first, acc);
        ci = ci2;

        phase2<ST, M + 1>(sW, sX, ii, y, w, lane, fl, s, ci, prev, first, acc);
    }
}

// ST = index element stride in int32 words (1 = int32, 2 = LE int64 with
// values < 2^31 -> read the low word).
template <int ST>
__device__ __forceinline__ void cfconv_body(
    const float4* __restrict__ X4, const float4* __restrict__ W4,
    const int* __restrict__ ii, const int* __restrict__ jj,
    float* __restrict__ y,
    float4 (&sW)[WPB][DS][2][32], float4 (&sX)[WPB][DS][2][32],
    int w, int lane, int fl, long long s, int cnt)
{
    const float4* wp = W4 + (size_t)s * F4 + fl;

    int    prev;
    bool   first = true;               // first segment may start before s
    float4 acc   = make_float4(0.f, 0.f, 0.f, 0.f);

    if (cnt == HALF) {
        // -------- pair-stage pipelined path --------
        // prologue: fill DS stages (one commit group per stage, 2 edges each)
        #pragma unroll
        for (int d = 0; d < DS; ++d) {
            int j0 = jj[(s + 2 * d)     * ST];
            int j1 = jj[(s + 2 * d + 1) * ST];
            cp16(&sW[w][d][0][lane], wp + (size_t)(2 * d)     * F4);
            cp16(&sW[w][d][1][lane], wp + (size_t)(2 * d + 1) * F4);
            cp16(&sX[w][d][0][lane], X4 + (size_t)j0 * F4 + fl);
            cp16(&sX[w][d][1][lane], X4 + (size_t)j1 * F4 + fl);
            CP_COMMIT();
        }
        int ci = ii[s * ST];

        prev = ci;

        // ---- phase 1: pairs 0..S-DS-1 — no guards, no clamps
        #pragma unroll 1
        for (int k = 0; k < S - DS; ++k) {
            cp_wait<DS - 1>();
            int st = k & (DS - 1);
            float4 wv0 = sW[w][st][0][lane];
            float4 xv0 = sX[w][st][0][lane];
            float4 wv1 = sW[w][st][1][lane];
            float4 xv1 = sX[w][st][1][lane];

            // prefetch pair k+DS (edges 2k+8, 2k+9 <= 63: always in-task)
            int e  = 2 * (k + DS);
            int j0 = jj[(s + e)     * ST];
            int j1 = jj[(s + e + 1) * ST];
            cp16(&sW[w][st][0][lane], wp + (size_t)e       * F4);
            cp16(&sW[w][st][1][lane], wp + (size_t)(e + 1) * F4);
            cp16(&sX[w][st][0][lane], X4 + (size_t)j0 * F4 + fl);
            cp16(&sX[w][st][1][lane], X4 + (size_t)j1 * F4 + fl);
            CP_COMMIT();

            // idx for this pair's 2nd edge and next pair's 1st (in-task)
            int ci1 = ii[(s + 2 * k + 1) * ST];
            int ci2 = ii[(s + 2 * k + 2) * ST];

            consume(y, fl, ci,  xv0, wv0, prev, first, acc);
            consume(y, fl, ci1, xv1, wv1, prev, first, acc);
            ci = ci2;
        }

        // ---- phase 2: last DS pairs — constant wait counts, no prefetch
        phase2<ST, 0>(sW, sX, ii, y, w, lane, fl, s, ci, prev, first, acc);
    } else {
        // -------- scalar tail path (at most one partial task) --------
        int    ic = ii[s * ST];
        int    jc = jj[s * ST];
        float4 wc = __ldcs(wp);
        float4 xc = X4[(size_t)jc * F4 + fl];
        prev = ic;
        for (int k = 1; k < cnt; ++k) {
            int    in_ = ii[(s + k) * ST];
            int    jn  = jj[(s + k) * ST];
            float4 wn  = __ldcs(wp + (size_t)k * F4);
            float4 xn  = X4[(size_t)jn * F4 + fl];
            consume(y, fl, ic, xc, wc, prev, first, acc);
            ic = in_; wc = wn; xc = xn;
        }
        consume(y, fl, ic, xc, wc, prev, first, acc);
    }

    // final segment may extend into the next task -> atomic
    red_add_f4(y + (size_t)prev * FEAT + fl * 4, acc);
}

__global__ __launch_bounds__(TPB) void cfconv_kernel(
    const float4* __restrict__ X4, const float4* __restrict__ W4,
    const void* __restrict__ ii_p, const void* __restrict__ jj_p,
    float* __restrict__ y, int E)
{
    __shared__ float4 sW[WPB][DS][2][32];
    __shared__ float4 sX[WPB][DS][2][32];

    int tid  = threadIdx.x;
    int w    = tid >> 5;
    int lane = tid & 31;
    int half = lane >> 4;
    int fl   = lane & 15;

    int gwarp = blockIdx.x * WPB + w;
    long long base = (long long)gwarp * CHUNK;
    if (base >= E) return;
    long long s = base + (long long)half * HALF;
    if (s >= E) return;
    long long se = s + HALF; if (se > E) se = E;
    int cnt = (int)(se - s);

    // dtype probe (uniform): LE int64 -> int32 word at odd position (E/2)|1 is
    // a zero high word; int32 -> sorted idx_i median ~N/2 != 0.
    int probe = reinterpret_cast<const int*>(ii_p)[(E / 2) | 1];
    const int* ii = reinterpret_cast<const int*>(ii_p);
    const int* jj = reinterpret_cast<const int*>(jj_p);
    if (probe == 0) {
        cfconv_body<2>(X4, W4, ii, jj, y, sW, sX, w, lane, fl, s, cnt);
    } else {
        cfconv_body<1>(X4, W4, ii, jj, y, sW, sX, w, lane, fl, s, cnt);
    }
}

extern "C" void kernel_launch(void* const* d_in, const int* in_sizes, int n_in,
                              void* d_out, int out_size)
{
    const float* x   = (const float*)d_in[0];   // [N, 64]
    const float* Wij = (const float*)d_in[1];   // [E, 64]
    const void*  ii  = d_in[2];                 // [E] int64 or int32
    const void*  jj  = d_in[3];                 // [E] int64 or int32
    float*       y   = (float*)d_out;           // [N, 64]

    int E = in_sizes[1] / FEAT;

    // zero output (memset node — graph-capturable)
    cudaMemsetAsync(d_out, 0, (size_t)out_size * sizeof(float), 0);

    int nwarps  = (E + CHUNK - 1) / CHUNK;
    int nblocks = (nwarps + WPB - 1) / WPB;
    cfconv_kernel<<<nblocks, TPB>>>((const float4*)x, (const float4*)Wij,
                                    ii, jj, y, E);
}